// round 14
// baseline (speedup 1.0000x reference)
#include <cuda_runtime.h>
#include <cuda_bf16.h>
#include <cstdint>
#include <math.h>

#define MAXN 50000
#define MAXE 640000
#define NPAD 53248
#define THR2 (0.01f * 0.01f)

// ================= device scratch =================
__device__ float g_agg_arcs[MAXN * 64];
__device__ float g_agg_nodes[MAXN * 128];
__device__ float g_agg_states[MAXN * 128];
__device__ float g_base[MAXN * 512];
__device__ float g_h1f[MAXN * 512];
__device__ float g_state[MAXN * 128];
__device__ float g_tmp[MAXN * 128];
__device__ int g_done;
__device__ int g_cont;
// CSR (by destination) of adj graph  (deg arrays padded for int4 scan)
__device__ int g_deg[NPAD];
__device__ int g_row_start[MAXN + 1];
__device__ int g_cursor[MAXN];
__device__ int g_e_src[MAXE];
__device__ float g_e_val[MAXE];
// CSR (by destination) of arc-agg graph (stores edge ids)
__device__ int g_deg2[NPAD];
__device__ int g_row_start2[MAXN + 1];
__device__ int g_cursor2[MAXN];
__device__ int g_a_eid[MAXE];
__device__ float g_a_val[MAXE];
// transposed+split weights [N,K] (k-major rows), bf16 hi/lo
__device__ __nv_bfloat16 g_ws1t_h[512 * 576];
__device__ __nv_bfloat16 g_ws1t_l[512 * 576];
__device__ __nv_bfloat16 g_ws2t_h[128 * 512];
__device__ __nv_bfloat16 g_ws2t_l[128 * 512];
__device__ __nv_bfloat16 g_wo1t_h[512 * 256];
__device__ __nv_bfloat16 g_wo1t_l[512 * 256];

// ================= setup: state copy + initial convergence check + zero deg =================
// NOTE: g_done/g_cont are NOT reset here (reset happens at the end of out_kernel of the
// previous run; globals are zero-initialized for the very first call).
__global__ void setup_kernel(const float* __restrict__ sinit, int Nn) {
    int idx = blockIdx.x * blockDim.x + threadIdx.x;
    if (idx < NPAD) { g_deg[idx] = 0; g_deg2[idx] = 0; }
    int w = idx >> 5, lane = idx & 31;
    if (w >= Nn) return;
    float4 a = ((const float4*)(sinit + (size_t)w * 128))[lane];
    ((float4*)(g_state + (size_t)w * 128))[lane] = a;
    float dx = a.x - 1.0f, dy = a.y - 1.0f, dz = a.z - 1.0f, dw = a.w - 1.0f;
    float d2 = dx*dx + dy*dy + dz*dz + dw*dw;
    #pragma unroll
    for (int off = 16; off > 0; off >>= 1)
        d2 += __shfl_xor_sync(0xffffffffu, d2, off);
    if (lane == 0 && d2 > THR2 * 128.0f && g_cont == 0) atomicOr(&g_cont, 1);
}

// ================= CSR build =================
__global__ void hist2_kernel(const int* __restrict__ dstA, const int* __restrict__ dstB,
                             int E) {
    int i = blockIdx.x * blockDim.x + threadIdx.x;
    if (i < E) atomicAdd(&g_deg[dstA[i]], 1);
    else if (i < 2 * E) atomicAdd(&g_deg2[dstB[i - E]], 1);
}

// gridDim=2: block 0 scans deg; block 1 scans deg2. int4-vectorized (deg padded, zeros).
__global__ void scan2_kernel(int Nn) {
    __shared__ int part[1024];
    const int* deg = blockIdx.x == 0 ? g_deg : g_deg2;
    int* row_start = blockIdx.x == 0 ? g_row_start : g_row_start2;
    int* cursor    = blockIdx.x == 0 ? g_cursor : g_cursor2;
    const int CH = 52;  // 13 int4 per thread; 52*1024 = 53248 = NPAD
    int t = threadIdx.x;
    int beg = t * CH;
    const int4* deg4 = (const int4*)deg;
    int s = 0;
    #pragma unroll
    for (int j = 0; j < 13; ++j) {
        int4 v = deg4[(beg >> 2) + j];
        s += v.x + v.y + v.z + v.w;
    }
    part[t] = s;
    __syncthreads();
    for (int off = 1; off < 1024; off <<= 1) {
        int v = (t >= off) ? part[t - off] : 0;
        __syncthreads();
        part[t] += v;
        __syncthreads();
    }
    int run = (t == 0) ? 0 : part[t - 1];
    #pragma unroll
    for (int j = 0; j < 13; ++j) {
        int4 v = deg4[(beg >> 2) + j];
        int b = beg + j * 4;
        int dv[4] = {v.x, v.y, v.z, v.w};
        #pragma unroll
        for (int k = 0; k < 4; ++k) {
            int i = b + k;
            if (i < Nn) { row_start[i] = run; cursor[i] = run; }
            run += dv[k];
        }
    }
    if (t == 1023) row_start[Nn] = part[1023];
}

__global__ void fill2_kernel(const int* __restrict__ adj_src, const int* __restrict__ adj_dst,
                             const float* __restrict__ adj_vals,
                             const int* __restrict__ an_dst, const float* __restrict__ an_vals,
                             int E) {
    int i = blockIdx.x * blockDim.x + threadIdx.x;
    if (i < E) {
        int pos = atomicAdd(&g_cursor[adj_dst[i]], 1);
        g_e_src[pos] = adj_src[i];
        g_e_val[pos] = adj_vals[i];
    } else if (i < 2 * E) {
        int e = i - E;
        int pos = atomicAdd(&g_cursor2[an_dst[e]], 1);
        g_a_eid[pos] = e;
        g_a_val[pos] = an_vals[e];
    }
}

// ================= CSR SPMM (R6-proven 2-edge unroll) =================
__global__ void scatter_csr_kernel(const float* __restrict__ dense,
                                   float* __restrict__ out, int Nn,
                                   const int* doneflag) {
    if (doneflag && *doneflag) return;
    int w = (blockIdx.x * blockDim.x + threadIdx.x) >> 5;
    int lane = threadIdx.x & 31;
    if (w >= Nn) return;
    int e = g_row_start[w], e1 = g_row_start[w + 1];
    float4 acc = make_float4(0.f, 0.f, 0.f, 0.f);
    for (; e + 1 < e1; e += 2) {
        int sA = g_e_src[e], sB = g_e_src[e + 1];
        float vA = g_e_val[e], vB = g_e_val[e + 1];
        float4 xA = ((const float4*)(dense + (size_t)sA * 128))[lane];
        float4 xB = ((const float4*)(dense + (size_t)sB * 128))[lane];
        acc.x += vA * xA.x + vB * xB.x;
        acc.y += vA * xA.y + vB * xB.y;
        acc.z += vA * xA.z + vB * xB.z;
        acc.w += vA * xA.w + vB * xB.w;
    }
    if (e < e1) {
        int sA = g_e_src[e];
        float vA = g_e_val[e];
        float4 xA = ((const float4*)(dense + (size_t)sA * 128))[lane];
        acc.x += vA * xA.x;
        acc.y += vA * xA.y;
        acc.z += vA * xA.z;
        acc.w += vA * xA.w;
    }
    ((float4*)(out + (size_t)w * 128))[lane] = acc;
}

// ================= one-time arc aggregation: CSR gather (no atomics) =================
__global__ void gather_arcs_kernel(const float* __restrict__ arcs, int Nn) {
    int w = (blockIdx.x * blockDim.x + threadIdx.x) >> 5;
    int lane = threadIdx.x & 31;
    if (w >= Nn) return;
    int e = g_row_start2[w], e1 = g_row_start2[w + 1];
    float2 acc = make_float2(0.f, 0.f);
    for (; e + 1 < e1; e += 2) {
        int iA = g_a_eid[e], iB = g_a_eid[e + 1];
        float vA = g_a_val[e], vB = g_a_val[e + 1];
        float2 xA = *(const float2*)(arcs + (size_t)iA * 66 + 2 + lane * 2);
        float2 xB = *(const float2*)(arcs + (size_t)iB * 66 + 2 + lane * 2);
        acc.x += vA * xA.x + vB * xB.x;
        acc.y += vA * xA.y + vB * xB.y;
    }
    if (e < e1) {
        int iA = g_a_eid[e];
        float vA = g_a_val[e];
        float2 xA = *(const float2*)(arcs + (size_t)iA * 66 + 2 + lane * 2);
        acc.x += vA * xA.x;
        acc.y += vA * xA.y;
    }
    *(float2*)(g_agg_arcs + (size_t)w * 64 + lane * 2) = acc;
}

// ================= weights transpose+split =================
__device__ __forceinline__ void tsplit_one(const float* W, __nv_bfloat16* Th,
                                           __nv_bfloat16* Tl, int K, int Nc, int i) {
    int k = i / Nc, n = i % Nc;
    float v = W[i];
    __nv_bfloat16 h = __float2bfloat16(v);
    Th[(size_t)n * K + k] = h;
    Tl[(size_t)n * K + k] = __float2bfloat16(v - __bfloat162float(h));
}
__global__ void transpose_all_kernel(const float* __restrict__ Ws1,
                                     const float* __restrict__ Ws2,
                                     const float* __restrict__ Wo1) {
    int i = blockIdx.x * blockDim.x + threadIdx.x;
    const int n1 = 576 * 512, n2 = n1 + 512 * 128, n3 = n2 + 256 * 512;
    if (i < n1) tsplit_one(Ws1, g_ws1t_h, g_ws1t_l, 576, 512, i);
    else if (i < n2) tsplit_one(Ws2, g_ws2t_h, g_ws2t_l, 512, 128, i - n1);
    else if (i < n3) tsplit_one(Wo1, g_wo1t_h, g_wo1t_l, 256, 512, i - n2);
}

__global__ void finalize_kernel() {
    if (!g_done && !g_cont) g_done = 1;
    g_cont = 0;
}

// ================= commit + check (R6-style, no ticket) =================
__global__ void commit_check_kernel(int Nn) {
    if (g_done) return;
    int w = (blockIdx.x * blockDim.x + threadIdx.x) >> 5;
    int lane = threadIdx.x & 31;
    if (w >= Nn) return;
    float4* ps = (float4*)(g_state + (size_t)w * 128);
    const float4* pt = (const float4*)(g_tmp + (size_t)w * 128);
    float4 o = ps[lane], nw = pt[lane];
    ps[lane] = nw;
    float dx = nw.x - o.x, dy = nw.y - o.y, dz = nw.z - o.z, dw = nw.w - o.w;
    float d2 = dx*dx + dy*dy + dz*dz + dw*dw;
    float n2 = o.x*o.x + o.y*o.y + o.z*o.z + o.w*o.w;
    #pragma unroll
    for (int off = 16; off > 0; off >>= 1) {
        d2 += __shfl_xor_sync(0xffffffffu, d2, off);
        n2 += __shfl_xor_sync(0xffffffffu, n2, off);
    }
    if (lane == 0 && d2 > THR2 * n2 && g_cont == 0) atomicOr(&g_cont, 1);
}

// ================= GEMM (R6-proven mainloop; NT = N-tile width template) =================
__device__ __forceinline__ void mma16816(float* d, const uint32_t* a, const uint32_t* b) {
    asm volatile(
        "mma.sync.aligned.m16n8k16.row.col.f32.bf16.bf16.f32 "
        "{%0,%1,%2,%3}, {%4,%5,%6,%7}, {%8,%9}, {%0,%1,%2,%3};"
        : "+f"(d[0]), "+f"(d[1]), "+f"(d[2]), "+f"(d[3])
        : "r"(a[0]), "r"(a[1]), "r"(a[2]), "r"(a[3]), "r"(b[0]), "r"(b[1]));
}
__device__ __forceinline__ void ldmx4(uint32_t* d, uint32_t addr) {
    asm volatile("ldmatrix.sync.aligned.m8n8.x4.shared.b16 {%0,%1,%2,%3}, [%4];"
                 : "=r"(d[0]), "=r"(d[1]), "=r"(d[2]), "=r"(d[3]) : "r"(addr));
}
__device__ __forceinline__ void cpa16(uint32_t dst, const void* src) {
    asm volatile("cp.async.cg.shared.global [%0], [%1], 16;" :: "r"(dst), "l"(src));
}

// smem: A [0,40960): stage*20480 + split*10240, pitch 80B (128 rows)
//       B [40960, 40960 + 2*NT*160): stage*(NT*160) + split*(NT*80), pitch 80B (NT rows)
template <int NPARTS, bool DOTANH, bool HASBASE, bool HASBIAS, int NT>
__global__ void __launch_bounds__(256, 2) gemm_db(
    int M, int ldC,
    const __nv_bfloat16* __restrict__ WTh, const __nv_bfloat16* __restrict__ WTl, int ldWT,
    const float* __restrict__ bias, const float* __restrict__ Cbase, float* __restrict__ C,
    const float* A0, int K0, int R0,
    const float* A1, int K1, int R1,
    const float* A2, int K2, int R2,
    const int* doneflag)
{
    if (doneflag && *doneflag) return;
    extern __shared__ char smem[];
    const uint32_t sbase = (uint32_t)__cvta_generic_to_shared(smem);
    constexpr int WTILE_N = NT / 2;   // per-warp N extent (2 warp cols)
    constexpr int NTI = WTILE_N / 8;  // n-tiles per warp
    constexpr int BSTG = NT * 160;    // bytes per B stage (hi+lo)
    constexpr int BLO = NT * 80;      // lo-split offset within stage

    const int tid = threadIdx.x;
    const int wid = tid >> 5, lane = tid & 31;
    const int wm0 = (wid & 3) * 32, wn0 = (wid >> 2) * WTILE_N;
    const int row0 = blockIdx.y * 128, col0 = blockIdx.x * NT;

    const float* Aps[3] = {A0, A1, A2};
    const int Ks[3] = {K0, K1, K2};
    const int Rs[3] = {R0, R1, R2};
    const int c0 = K0 >> 5, c1 = K1 >> 5;
    const int c2 = (NPARTS > 2) ? (K2 >> 5) : 0;
    const int CT = c0 + c1 + c2;

    const int arow = tid >> 1, ahalf = tid & 1;
    float acc[2][NTI][4] = {};
    float av[16];

    auto partof = [&](int ci, const float*& A, int& Kp, int& R, int& kc) {
        if (ci < c0) { A = Aps[0]; Kp = Ks[0]; R = Rs[0]; kc = ci << 5; }
        else if (ci < c0 + c1) { A = Aps[1]; Kp = Ks[1]; R = Rs[1]; kc = (ci - c0) << 5; }
        else { A = Aps[2]; Kp = Ks[2]; R = Rs[2]; kc = (ci - c0 - c1) << 5; }
    };
    auto ldA = [&](int ci) {
        const float* A; int Kp, R, kc;
        partof(ci, A, Kp, R, kc);
        int gr = row0 + arow;
        if (gr < M) {
            const float4* p = (const float4*)(A + (size_t)gr * Kp + kc + ahalf * 16);
            #pragma unroll
            for (int i = 0; i < 4; i++) {
                float4 f = p[i];
                av[4*i] = f.x; av[4*i+1] = f.y; av[4*i+2] = f.z; av[4*i+3] = f.w;
            }
        } else {
            #pragma unroll
            for (int i = 0; i < 16; i++) av[i] = 0.0f;
        }
    };
    auto stA = [&](int stage) {
        uint32_t H[8], L[8];
        #pragma unroll
        for (int i = 0; i < 8; i++) {
            __nv_bfloat162 h2 = __floats2bfloat162_rn(av[2*i], av[2*i+1]);
            float r0 = av[2*i] - __low2float(h2);
            float r1 = av[2*i+1] - __high2float(h2);
            __nv_bfloat162 l2 = __floats2bfloat162_rn(r0, r1);
            H[i] = *reinterpret_cast<uint32_t*>(&h2);
            L[i] = *reinterpret_cast<uint32_t*>(&l2);
        }
        char* dh = smem + stage * 20480 + arow * 80 + ahalf * 32;
        *(uint4*)dh = make_uint4(H[0], H[1], H[2], H[3]);
        *(uint4*)(dh + 16) = make_uint4(H[4], H[5], H[6], H[7]);
        char* dl = dh + 10240;
        *(uint4*)dl = make_uint4(L[0], L[1], L[2], L[3]);
        *(uint4*)(dl + 16) = make_uint4(L[4], L[5], L[6], L[7]);
    };
    auto cpB = [&](int ci, int stage) {
        if (arow >= NT) return;
        const float* A; int Kp, R, kc;
        partof(ci, A, Kp, R, kc);
        size_t g = (size_t)(col0 + arow) * ldWT + R + kc + ahalf * 16;
        uint32_t dH = sbase + 40960 + stage * BSTG + arow * 80 + ahalf * 32;
        cpa16(dH, WTh + g);
        cpa16(dH + 16, WTh + g + 8);
        uint32_t dL = dH + BLO;
        cpa16(dL, WTl + g);
        cpa16(dL + 16, WTl + g + 8);
    };

    const uint32_t aoff = (uint32_t)((wm0 + (lane & 15)) * 80 + (lane >> 4) * 16);
    const int bl = lane & 7, grp = lane >> 3;
    const uint32_t boff = (uint32_t)((wn0 + bl) * 80 + (grp & 1) * 16 + (grp >> 1) * BLO);

    cpB(0, 0);
    asm volatile("cp.async.commit_group;" ::: "memory");
    ldA(0);

    for (int ci = 0; ci < CT; ++ci) {
        const int st = ci & 1;
        stA(st);
        if (ci + 1 < CT) cpB(ci + 1, st ^ 1);
        asm volatile("cp.async.commit_group;" ::: "memory");
        if (ci + 1 < CT) ldA(ci + 1);
        asm volatile("cp.async.wait_group 1;" ::: "memory");
        __syncthreads();

        const uint32_t stgA = sbase + st * 20480;
        const uint32_t stgB = sbase + 40960 + st * BSTG;
        #pragma unroll
        for (int k0 = 0; k0 < 64; k0 += 32) {
            uint32_t Ah[2][4], Al[2][4];
            #pragma unroll
            for (int mt = 0; mt < 2; ++mt) {
                uint32_t ad = stgA + aoff + mt * 1280 + k0;
                ldmx4(Ah[mt], ad);
                ldmx4(Al[mt], ad + 10240);
            }
            #pragma unroll
            for (int nt = 0; nt < NTI; ++nt) {
                uint32_t bb[4];
                ldmx4(bb, stgB + boff + nt * 640 + k0);
                #pragma unroll
                for (int mt = 0; mt < 2; ++mt) {
                    mma16816(acc[mt][nt], Ah[mt], bb);
                    mma16816(acc[mt][nt], Ah[mt], bb + 2);
                    mma16816(acc[mt][nt], Al[mt], bb);
                }
            }
        }
        __syncthreads();
    }

    const int g = lane >> 2, tq = lane & 3;
    #pragma unroll
    for (int mt = 0; mt < 2; ++mt) {
        #pragma unroll
        for (int nt = 0; nt < NTI; ++nt) {
            int r = row0 + wm0 + mt * 16 + g;
            int c = col0 + wn0 + nt * 8 + tq * 2;
            #pragma unroll
            for (int half = 0; half < 2; ++half) {
                int row = r + half * 8;
                if (row >= M) continue;
                #pragma unroll
                for (int j = 0; j < 2; ++j) {
                    int col = c + j;
                    float v = acc[mt][nt][half * 2 + j];
                    if (HASBIAS) v += bias[col];
                    if (HASBASE) v += Cbase[(size_t)row * ldC + col];
                    if (DOTANH) v = tanhf(v);
                    C[(size_t)row * ldC + col] = v;
                }
            }
        }
    }
}

// ================= final output (+ flag reset for next replay) =================
__global__ void out_kernel(const float* __restrict__ Wo2,
                           const float* __restrict__ bo2,
                           const unsigned int* __restrict__ m1,
                           const unsigned int* __restrict__ m2,
                           float* __restrict__ out, int Nn) {
    if (blockIdx.x == 0 && threadIdx.x == 0) { g_done = 0; g_cont = 0; }
    int w = (blockIdx.x * blockDim.x + threadIdx.x) >> 5;
    int lane = threadIdx.x & 31;
    if (w >= Nn) return;
    float acc[7] = {0, 0, 0, 0, 0, 0, 0};
    const float* h = g_h1f + (size_t)w * 512;
    for (int k = lane; k < 512; k += 32) {
        float hv = h[k];
        const float* wr = Wo2 + (size_t)k * 7;
        #pragma unroll
        for (int o = 0; o < 7; o++) acc[o] += hv * wr[o];
    }
    #pragma unroll
    for (int o = 0; o < 7; o++)
        #pragma unroll
        for (int off = 16; off > 0; off >>= 1)
            acc[o] += __shfl_xor_sync(0xffffffffu, acc[o], off);
    float msk = (m1[w] != 0u && m2[w] != 0u) ? 1.0f : 0.0f;
    if (lane < 7) out[(size_t)w * 7 + lane] = (acc[lane] + bo2[lane]) * msk;
}

// ================= host launch =================
extern "C" void kernel_launch(void* const* d_in, const int* in_sizes, int n_in,
                              void* d_out, int out_size) {
    const float* nodes = (const float*)d_in[0];
    const float* arcs  = (const float*)d_in[1];
    const unsigned int* set_mask = (const unsigned int*)d_in[2];
    const unsigned int* output_mask = (const unsigned int*)d_in[3];
    const int* adj_src = (const int*)d_in[4];
    const int* adj_dst = (const int*)d_in[5];
    const float* adj_vals = (const float*)d_in[6];
    const int* an_dst = (const int*)d_in[7];
    const float* an_vals = (const float*)d_in[8];
    const float* state_init = (const float*)d_in[9];
    const float* Ws1 = (const float*)d_in[10];
    const float* bs1 = (const float*)d_in[11];
    const float* Ws2 = (const float*)d_in[12];
    const float* bs2 = (const float*)d_in[13];
    const float* Wo1 = (const float*)d_in[14];
    const float* bo1 = (const float*)d_in[15];
    const float* Wo2 = (const float*)d_in[16];
    const float* bo2 = (const float*)d_in[17];
    float* out = (float*)d_out;

    int Nn = in_sizes[0] / 128;   // 50000
    int E  = in_sizes[4];         // 640000

    float *p_agg_states, *p_base, *p_h1f, *p_state, *p_tmp;
    int* p_done;
    __nv_bfloat16 *p_ws1t_h, *p_ws1t_l, *p_ws2t_h, *p_ws2t_l, *p_wo1t_h, *p_wo1t_l;
    float *p_agg_nodes, *p_agg_arcs;
    cudaGetSymbolAddress((void**)&p_agg_states, g_agg_states);
    cudaGetSymbolAddress((void**)&p_base, g_base);
    cudaGetSymbolAddress((void**)&p_h1f, g_h1f);
    cudaGetSymbolAddress((void**)&p_state, g_state);
    cudaGetSymbolAddress((void**)&p_tmp, g_tmp);
    cudaGetSymbolAddress((void**)&p_done, g_done);
    cudaGetSymbolAddress((void**)&p_agg_nodes, g_agg_nodes);
    cudaGetSymbolAddress((void**)&p_agg_arcs, g_agg_arcs);
    cudaGetSymbolAddress((void**)&p_ws1t_h, g_ws1t_h);
    cudaGetSymbolAddress((void**)&p_ws1t_l, g_ws1t_l);
    cudaGetSymbolAddress((void**)&p_ws2t_h, g_ws2t_h);
    cudaGetSymbolAddress((void**)&p_ws2t_l, g_ws2t_l);
    cudaGetSymbolAddress((void**)&p_wo1t_h, g_wo1t_h);
    cudaGetSymbolAddress((void**)&p_wo1t_l, g_wo1t_l);

    auto kBase  = gemm_db<3, false, false, true,  128>;
    auto kIter1 = gemm_db<2, true,  true,  false, 128>;
    auto kIter2 = gemm_db<1, true,  false, true,  64 >;
    auto kFinal = gemm_db<2, true,  false, true,  128>;
    const int SMEM128 = 40960 + 2 * 128 * 160;  // 81920
    const int SMEM64  = 40960 + 2 * 64 * 160;   // 61440
    cudaFuncSetAttribute(kBase,  cudaFuncAttributeMaxDynamicSharedMemorySize, SMEM128);
    cudaFuncSetAttribute(kIter1, cudaFuncAttributeMaxDynamicSharedMemorySize, SMEM128);
    cudaFuncSetAttribute(kIter2, cudaFuncAttributeMaxDynamicSharedMemorySize, SMEM64);
    cudaFuncSetAttribute(kFinal, cudaFuncAttributeMaxDynamicSharedMemorySize, SMEM128);

    int edge2Blocks = (2 * E + 255) / 256;
    int nodeWarpBlocks = (Nn * 32 + 255) / 256;
    int mtiles = (Nn + 127) / 128;
    dim3 g512(4, mtiles);     // NT=128 x 4 cols
    dim3 g128n64(2, mtiles);  // NT=64 x 2 cols

    // ---- one-time setup ----
    setup_kernel<<<nodeWarpBlocks, 256>>>(state_init, Nn);
    hist2_kernel<<<edge2Blocks, 256>>>(adj_dst, an_dst, E);
    scan2_kernel<<<2, 1024>>>(Nn);
    fill2_kernel<<<edge2Blocks, 256>>>(adj_src, adj_dst, adj_vals, an_dst, an_vals, E);
    transpose_all_kernel<<<(491520 + 255) / 256, 256>>>(Ws1, Ws2, Wo1);
    gather_arcs_kernel<<<nodeWarpBlocks, 256>>>(arcs, Nn);
    scatter_csr_kernel<<<nodeWarpBlocks, 256>>>(nodes, p_agg_nodes, Nn, nullptr);

    // base = bs1 + nodes@Ws1[128:256] + agg_nodes@Ws1[384:512] + agg_arcs@Ws1[512:576]
    kBase<<<g512, 256, SMEM128>>>(
        Nn, 512, p_ws1t_h, p_ws1t_l, 576, bs1, nullptr, p_base,
        nodes, 128, 128,
        p_agg_nodes, 128, 384,
        p_agg_arcs, 64, 512, nullptr);

    // ---- fixed-point loop (R6-proven shape) ----
    for (int it = 0; it < 10; ++it) {
        finalize_kernel<<<1, 1>>>();
        scatter_csr_kernel<<<nodeWarpBlocks, 256>>>(p_state, p_agg_states, Nn, p_done);
        kIter1<<<g512, 256, SMEM128>>>(
            Nn, 512, p_ws1t_h, p_ws1t_l, 576, nullptr, p_base, p_h1f,
            p_state, 128, 0,
            p_agg_states, 128, 256,
            nullptr, 0, 0, p_done);
        kIter2<<<g128n64, 256, SMEM64>>>(
            Nn, 128, p_ws2t_h, p_ws2t_l, 512, bs2, nullptr, p_tmp,
            p_h1f, 512, 0,
            nullptr, 0, 0,
            nullptr, 0, 0, p_done);
        commit_check_kernel<<<nodeWarpBlocks, 256>>>(Nn);
    }

    // h1f = tanh(state@Wo1[0:128] + nodes@Wo1[128:256] + bo1)
    kFinal<<<g512, 256, SMEM128>>>(
        Nn, 512, p_wo1t_h, p_wo1t_l, 256, bo1, nullptr, p_h1f,
        p_state, 128, 0,
        nodes, 128, 128,
        nullptr, 0, 0, nullptr);

    out_kernel<<<nodeWarpBlocks, 256>>>(Wo2, bo2, set_mask, output_mask, out, Nn);
}

// round 16
// speedup vs baseline: 1.1180x; 1.1180x over previous
#include <cuda_runtime.h>
#include <cuda_bf16.h>
#include <cstdint>
#include <math.h>

#define MAXN 50000
#define MAXE 640000
#define NPAD 53248
#define THR2 (0.01f * 0.01f)

// ================= device scratch =================
__device__ float g_agg_arcs[MAXN * 64];
__device__ float g_agg_nodes[MAXN * 128];
__device__ float g_agg_states[MAXN * 128];
__device__ float g_base[MAXN * 512];
__device__ float g_h1f[MAXN * 512];
__device__ float g_state[MAXN * 128];
__device__ float g_tmp[MAXN * 128];
__device__ int g_done;
__device__ int g_cont2[2];   // parity slots: commit(it) -> slot (it+1)&1; scatter(it) reads slot it&1
// CSR (by destination) of adj graph  (deg arrays padded for int4 scan)
__device__ int g_deg[NPAD];
__device__ int g_row_start[MAXN + 1];
__device__ int g_cursor[MAXN];
__device__ int g_e_src[MAXE];
__device__ float g_e_val[MAXE];
// CSR (by destination) of arc-agg graph (stores edge ids)
__device__ int g_deg2[NPAD];
__device__ int g_row_start2[MAXN + 1];
__device__ int g_cursor2[MAXN];
__device__ int g_a_eid[MAXE];
__device__ float g_a_val[MAXE];
// transposed+split weights [N,K] (k-major rows), bf16 hi/lo
__device__ __nv_bfloat16 g_ws1t_h[512 * 576];
__device__ __nv_bfloat16 g_ws1t_l[512 * 576];
__device__ __nv_bfloat16 g_ws2t_h[128 * 512];
__device__ __nv_bfloat16 g_ws2t_l[128 * 512];
__device__ __nv_bfloat16 g_wo1t_h[512 * 256];
__device__ __nv_bfloat16 g_wo1t_l[512 * 256];

// ================= setup: state copy + initial convergence check + zero deg =================
// g_done/g_cont2 reset happens at end of out_kernel (previous replay); zero-init first run.
__global__ void setup_kernel(const float* __restrict__ sinit, int Nn) {
    int idx = blockIdx.x * blockDim.x + threadIdx.x;
    if (idx < NPAD) { g_deg[idx] = 0; g_deg2[idx] = 0; }
    int w = idx >> 5, lane = idx & 31;
    if (w >= Nn) return;
    float4 a = ((const float4*)(sinit + (size_t)w * 128))[lane];
    ((float4*)(g_state + (size_t)w * 128))[lane] = a;
    float dx = a.x - 1.0f, dy = a.y - 1.0f, dz = a.z - 1.0f, dw = a.w - 1.0f;
    float d2 = dx*dx + dy*dy + dz*dz + dw*dw;
    #pragma unroll
    for (int off = 16; off > 0; off >>= 1)
        d2 += __shfl_xor_sync(0xffffffffu, d2, off);
    if (lane == 0 && d2 > THR2 * 128.0f && g_cont2[0] == 0) atomicOr(&g_cont2[0], 1);
}

// ================= CSR build =================
__global__ void hist2_kernel(const int* __restrict__ dstA, const int* __restrict__ dstB,
                             int E) {
    int i = blockIdx.x * blockDim.x + threadIdx.x;
    if (i < E) atomicAdd(&g_deg[dstA[i]], 1);
    else if (i < 2 * E) atomicAdd(&g_deg2[dstB[i - E]], 1);
}

// gridDim=2: block 0 scans deg; block 1 scans deg2. int4-vectorized (deg padded, zeros).
__global__ void scan2_kernel(int Nn) {
    __shared__ int part[1024];
    const int* deg = blockIdx.x == 0 ? g_deg : g_deg2;
    int* row_start = blockIdx.x == 0 ? g_row_start : g_row_start2;
    int* cursor    = blockIdx.x == 0 ? g_cursor : g_cursor2;
    const int CH = 52;
    int t = threadIdx.x;
    int beg = t * CH;
    const int4* deg4 = (const int4*)deg;
    int s = 0;
    #pragma unroll
    for (int j = 0; j < 13; ++j) {
        int4 v = deg4[(beg >> 2) + j];
        s += v.x + v.y + v.z + v.w;
    }
    part[t] = s;
    __syncthreads();
    for (int off = 1; off < 1024; off <<= 1) {
        int v = (t >= off) ? part[t - off] : 0;
        __syncthreads();
        part[t] += v;
        __syncthreads();
    }
    int run = (t == 0) ? 0 : part[t - 1];
    #pragma unroll
    for (int j = 0; j < 13; ++j) {
        int4 v = deg4[(beg >> 2) + j];
        int b = beg + j * 4;
        int dv[4] = {v.x, v.y, v.z, v.w};
        #pragma unroll
        for (int k = 0; k < 4; ++k) {
            int i = b + k;
            if (i < Nn) { row_start[i] = run; cursor[i] = run; }
            run += dv[k];
        }
    }
    if (t == 1023) row_start[Nn] = part[1023];
}

__global__ void fill2_kernel(const int* __restrict__ adj_src, const int* __restrict__ adj_dst,
                             const float* __restrict__ adj_vals,
                             const int* __restrict__ an_dst, const float* __restrict__ an_vals,
                             int E) {
    int i = blockIdx.x * blockDim.x + threadIdx.x;
    if (i < E) {
        int pos = atomicAdd(&g_cursor[adj_dst[i]], 1);
        g_e_src[pos] = adj_src[i];
        g_e_val[pos] = adj_vals[i];
    } else if (i < 2 * E) {
        int e = i - E;
        int pos = atomicAdd(&g_cursor2[an_dst[e]], 1);
        g_a_eid[pos] = e;
        g_a_val[pos] = an_vals[e];
    }
}

// ================= CSR SPMM + fused finalize (it>=0) =================
// it < 0: unconditional (setup use). it >= 0: gate on eff_done = g_done || cont2[it&1]==0.
// Block 0 thread 0 performs the done transition and resets the next cont slot.
__global__ void scatter_csr_kernel(const float* __restrict__ dense,
                                   float* __restrict__ out, int Nn, int it) {
    if (it >= 0) {
        int p = it & 1;
        if (blockIdx.x == 0 && threadIdx.x == 0) {
            if (!g_done && g_cont2[p] == 0) g_done = 1;
            g_cont2[p ^ 1] = 0;   // reset slot for commit_check(it)
        }
        if (g_done || g_cont2[p] == 0) return;  // cont2[p] stable during this kernel
    }
    int w = (blockIdx.x * blockDim.x + threadIdx.x) >> 5;
    int lane = threadIdx.x & 31;
    if (w >= Nn) return;
    int e = g_row_start[w], e1 = g_row_start[w + 1];
    float4 acc = make_float4(0.f, 0.f, 0.f, 0.f);
    for (; e + 1 < e1; e += 2) {
        int sA = g_e_src[e], sB = g_e_src[e + 1];
        float vA = g_e_val[e], vB = g_e_val[e + 1];
        float4 xA = ((const float4*)(dense + (size_t)sA * 128))[lane];
        float4 xB = ((const float4*)(dense + (size_t)sB * 128))[lane];
        acc.x += vA * xA.x + vB * xB.x;
        acc.y += vA * xA.y + vB * xB.y;
        acc.z += vA * xA.z + vB * xB.z;
        acc.w += vA * xA.w + vB * xB.w;
    }
    if (e < e1) {
        int sA = g_e_src[e];
        float vA = g_e_val[e];
        float4 xA = ((const float4*)(dense + (size_t)sA * 128))[lane];
        acc.x += vA * xA.x;
        acc.y += vA * xA.y;
        acc.z += vA * xA.z;
        acc.w += vA * xA.w;
    }
    ((float4*)(out + (size_t)w * 128))[lane] = acc;
}

// ================= one-time arc aggregation: CSR gather =================
__global__ void gather_arcs_kernel(const float* __restrict__ arcs, int Nn) {
    int w = (blockIdx.x * blockDim.x + threadIdx.x) >> 5;
    int lane = threadIdx.x & 31;
    if (w >= Nn) return;
    int e = g_row_start2[w], e1 = g_row_start2[w + 1];
    float2 acc = make_float2(0.f, 0.f);
    for (; e + 1 < e1; e += 2) {
        int iA = g_a_eid[e], iB = g_a_eid[e + 1];
        float vA = g_a_val[e], vB = g_a_val[e + 1];
        float2 xA = *(const float2*)(arcs + (size_t)iA * 66 + 2 + lane * 2);
        float2 xB = *(const float2*)(arcs + (size_t)iB * 66 + 2 + lane * 2);
        acc.x += vA * xA.x + vB * xB.x;
        acc.y += vA * xA.y + vB * xB.y;
    }
    if (e < e1) {
        int iA = g_a_eid[e];
        float vA = g_a_val[e];
        float2 xA = *(const float2*)(arcs + (size_t)iA * 66 + 2 + lane * 2);
        acc.x += vA * xA.x;
        acc.y += vA * xA.y;
    }
    *(float2*)(g_agg_arcs + (size_t)w * 64 + lane * 2) = acc;
}

// ================= weights transpose+split =================
__device__ __forceinline__ void tsplit_one(const float* W, __nv_bfloat16* Th,
                                           __nv_bfloat16* Tl, int K, int Nc, int i) {
    int k = i / Nc, n = i % Nc;
    float v = W[i];
    __nv_bfloat16 h = __float2bfloat16(v);
    Th[(size_t)n * K + k] = h;
    Tl[(size_t)n * K + k] = __float2bfloat16(v - __bfloat162float(h));
}
__global__ void transpose_all_kernel(const float* __restrict__ Ws1,
                                     const float* __restrict__ Ws2,
                                     const float* __restrict__ Wo1) {
    int i = blockIdx.x * blockDim.x + threadIdx.x;
    const int n1 = 576 * 512, n2 = n1 + 512 * 128, n3 = n2 + 256 * 512;
    if (i < n1) tsplit_one(Ws1, g_ws1t_h, g_ws1t_l, 576, 512, i);
    else if (i < n2) tsplit_one(Ws2, g_ws2t_h, g_ws2t_l, 512, 128, i - n1);
    else if (i < n3) tsplit_one(Wo1, g_wo1t_h, g_wo1t_l, 256, 512, i - n2);
}

// ================= commit + check (sets cont slot for next iter) =================
__global__ void commit_check_kernel(int Nn, int it) {
    if (g_done) return;   // set by scatter(it) if converged; visible across launch boundary
    int w = (blockIdx.x * blockDim.x + threadIdx.x) >> 5;
    int lane = threadIdx.x & 31;
    if (w >= Nn) return;
    float4* ps = (float4*)(g_state + (size_t)w * 128);
    const float4* pt = (const float4*)(g_tmp + (size_t)w * 128);
    float4 o = ps[lane], nw = pt[lane];
    ps[lane] = nw;
    float dx = nw.x - o.x, dy = nw.y - o.y, dz = nw.z - o.z, dw = nw.w - o.w;
    float d2 = dx*dx + dy*dy + dz*dz + dw*dw;
    float n2 = o.x*o.x + o.y*o.y + o.z*o.z + o.w*o.w;
    #pragma unroll
    for (int off = 16; off > 0; off >>= 1) {
        d2 += __shfl_xor_sync(0xffffffffu, d2, off);
        n2 += __shfl_xor_sync(0xffffffffu, n2, off);
    }
    int slot = (it + 1) & 1;
    if (lane == 0 && d2 > THR2 * n2 && g_cont2[slot] == 0) atomicOr(&g_cont2[slot], 1);
}

// ================= GEMM: single-sync mainloop (3-stage B, 2-stage A) =================
__device__ __forceinline__ void mma16816(float* d, const uint32_t* a, const uint32_t* b) {
    asm volatile(
        "mma.sync.aligned.m16n8k16.row.col.f32.bf16.bf16.f32 "
        "{%0,%1,%2,%3}, {%4,%5,%6,%7}, {%8,%9}, {%0,%1,%2,%3};"
        : "+f"(d[0]), "+f"(d[1]), "+f"(d[2]), "+f"(d[3])
        : "r"(a[0]), "r"(a[1]), "r"(a[2]), "r"(a[3]), "r"(b[0]), "r"(b[1]));
}
__device__ __forceinline__ void ldmx4(uint32_t* d, uint32_t addr) {
    asm volatile("ldmatrix.sync.aligned.m8n8.x4.shared.b16 {%0,%1,%2,%3}, [%4];"
                 : "=r"(d[0]), "=r"(d[1]), "=r"(d[2]), "=r"(d[3]) : "r"(addr));
}
__device__ __forceinline__ void cpa16(uint32_t dst, const void* src) {
    asm volatile("cp.async.cg.shared.global [%0], [%1], 16;" :: "r"(dst), "l"(src));
}

// smem: A [0,40960): stage(2)*20480 + split*10240, pitch 80B (128 rows)
//       B [40960, 40960+3*NT*160): stage(3)*(NT*160) + split*(NT*80), pitch 80B
template <int NPARTS, bool DOTANH, bool HASBASE, bool HASBIAS, int NT>
__global__ void __launch_bounds__(256, 2) gemm_db(
    int M, int ldC,
    const __nv_bfloat16* __restrict__ WTh, const __nv_bfloat16* __restrict__ WTl, int ldWT,
    const float* __restrict__ bias, const float* __restrict__ Cbase, float* __restrict__ C,
    const float* A0, int K0, int R0,
    const float* A1, int K1, int R1,
    const float* A2, int K2, int R2,
    const int* doneflag)
{
    if (doneflag && *doneflag) return;
    extern __shared__ char smem[];
    const uint32_t sbase = (uint32_t)__cvta_generic_to_shared(smem);
    constexpr int WTILE_N = NT / 2;
    constexpr int NTI = WTILE_N / 8;
    constexpr int BSTG = NT * 160;
    constexpr int BLO = NT * 80;

    const int tid = threadIdx.x;
    const int wid = tid >> 5, lane = tid & 31;
    const int wm0 = (wid & 3) * 32, wn0 = (wid >> 2) * WTILE_N;
    const int row0 = blockIdx.y * 128, col0 = blockIdx.x * NT;

    const float* Aps[3] = {A0, A1, A2};
    const int Ks[3] = {K0, K1, K2};
    const int Rs[3] = {R0, R1, R2};
    const int c0 = K0 >> 5, c1 = K1 >> 5;
    const int c2 = (NPARTS > 2) ? (K2 >> 5) : 0;
    const int CT = c0 + c1 + c2;

    const int arow = tid >> 1, ahalf = tid & 1;
    float acc[2][NTI][4] = {};
    float av[16];

    auto partof = [&](int ci, const float*& A, int& Kp, int& R, int& kc) {
        if (ci < c0) { A = Aps[0]; Kp = Ks[0]; R = Rs[0]; kc = ci << 5; }
        else if (ci < c0 + c1) { A = Aps[1]; Kp = Ks[1]; R = Rs[1]; kc = (ci - c0) << 5; }
        else { A = Aps[2]; Kp = Ks[2]; R = Rs[2]; kc = (ci - c0 - c1) << 5; }
    };
    auto ldA = [&](int ci) {
        const float* A; int Kp, R, kc;
        partof(ci, A, Kp, R, kc);
        int gr = row0 + arow;
        if (gr < M) {
            const float4* p = (const float4*)(A + (size_t)gr * Kp + kc + ahalf * 16);
            #pragma unroll
            for (int i = 0; i < 4; i++) {
                float4 f = p[i];
                av[4*i] = f.x; av[4*i+1] = f.y; av[4*i+2] = f.z; av[4*i+3] = f.w;
            }
        } else {
            #pragma unroll
            for (int i = 0; i < 16; i++) av[i] = 0.0f;
        }
    };
    auto stA = [&](int stage) {
        uint32_t H[8], L[8];
        #pragma unroll
        for (int i = 0; i < 8; i++) {
            __nv_bfloat162 h2 = __floats2bfloat162_rn(av[2*i], av[2*i+1]);
            float r0 = av[2*i] - __low2float(h2);
            float r1 = av[2*i+1] - __high2float(h2);
            __nv_bfloat162 l2 = __floats2bfloat162_rn(r0, r1);
            H[i] = *reinterpret_cast<uint32_t*>(&h2);
            L[i] = *reinterpret_cast<uint32_t*>(&l2);
        }
        char* dh = smem + stage * 20480 + arow * 80 + ahalf * 32;
        *(uint4*)dh = make_uint4(H[0], H[1], H[2], H[3]);
        *(uint4*)(dh + 16) = make_uint4(H[4], H[5], H[6], H[7]);
        char* dl = dh + 10240;
        *(uint4*)dl = make_uint4(L[0], L[1], L[2], L[3]);
        *(uint4*)(dl + 16) = make_uint4(L[4], L[5], L[6], L[7]);
    };
    auto cpB = [&](int ci, int stage) {
        if (arow >= NT) return;
        const float* A; int Kp, R, kc;
        partof(ci, A, Kp, R, kc);
        size_t g = (size_t)(col0 + arow) * ldWT + R + kc + ahalf * 16;
        uint32_t dH = sbase + 40960 + stage * BSTG + arow * 80 + ahalf * 32;
        cpa16(dH, WTh + g);
        cpa16(dH + 16, WTh + g + 8);
        uint32_t dL = dH + BLO;
        cpa16(dL, WTl + g);
        cpa16(dL + 16, WTl + g + 8);
    };

    const uint32_t aoff = (uint32_t)((wm0 + (lane & 15)) * 80 + (lane >> 4) * 16);
    const int bl = lane & 7, grp = lane >> 3;
    const uint32_t boff = (uint32_t)((wn0 + bl) * 80 + (grp & 1) * 16 + (grp >> 1) * BLO);

    cpB(0, 0);
    asm volatile("cp.async.commit_group;" ::: "memory");
    if (1 < CT) cpB(1, 1);
    asm volatile("cp.async.commit_group;" ::: "memory");
    ldA(0);

    for (int ci = 0; ci < CT; ++ci) {
        const int st = ci & 1;
        const int bs = ci % 3;
        stA(st);
        if (ci + 1 < CT) ldA(ci + 1);
        asm volatile("cp.async.wait_group 1;" ::: "memory");
        __syncthreads();
        if (ci + 2 < CT) cpB(ci + 2, (ci + 2) % 3);
        asm volatile("cp.async.commit_group;" ::: "memory");

        const uint32_t stgA = sbase + st * 20480;
        const uint32_t stgB = sbase + 40960 + bs * BSTG;
        #pragma unroll
        for (int k0 = 0; k0 < 64; k0 += 32) {
            uint32_t Ah[2][4], Al[2][4];
            #pragma unroll
            for (int mt = 0; mt < 2; ++mt) {
                uint32_t ad = stgA + aoff + mt * 1280 + k0;
                ldmx4(Ah[mt], ad);
                ldmx4(Al[mt], ad + 10240);
            }
            #pragma unroll
            for (int nt = 0; nt < NTI; ++nt) {
                uint32_t bb[4];
                ldmx4(bb, stgB + boff + nt * 640 + k0);
                #pragma unroll
                for (int mt = 0; mt < 2; ++mt) {
                    mma16816(acc[mt][nt], Ah[mt], bb);
                    mma16816(acc[mt][nt], Ah[mt], bb + 2);
                    mma16816(acc[mt][nt], Al[mt], bb);
                }
            }
        }
    }

    const int g = lane >> 2, tq = lane & 3;
    #pragma unroll
    for (int mt = 0; mt < 2; ++mt) {
        #pragma unroll
        for (int nt = 0; nt < NTI; ++nt) {
            int r = row0 + wm0 + mt * 16 + g;
            int c = col0 + wn0 + nt * 8 + tq * 2;
            #pragma unroll
            for (int half = 0; half < 2; ++half) {
                int row = r + half * 8;
                if (row >= M) continue;
                #pragma unroll
                for (int j = 0; j < 2; ++j) {
                    int col = c + j;
                    float v = acc[mt][nt][half * 2 + j];
                    if (HASBIAS) v += bias[col];
                    if (HASBASE) v += Cbase[(size_t)row * ldC + col];
                    if (DOTANH) v = tanhf(v);
                    C[(size_t)row * ldC + col] = v;
                }
            }
        }
    }
}

// ================= final output (+ flag reset for next replay) =================
__global__ void out_kernel(const float* __restrict__ Wo2,
                           const float* __restrict__ bo2,
                           const unsigned int* __restrict__ m1,
                           const unsigned int* __restrict__ m2,
                           float* __restrict__ out, int Nn) {
    if (blockIdx.x == 0 && threadIdx.x == 0) {
        g_done = 0; g_cont2[0] = 0; g_cont2[1] = 0;
    }
    int w = (blockIdx.x * blockDim.x + threadIdx.x) >> 5;
    int lane = threadIdx.x & 31;
    if (w >= Nn) return;
    float acc[7] = {0, 0, 0, 0, 0, 0, 0};
    const float* h = g_h1f + (size_t)w * 512;
    for (int k = lane; k < 512; k += 32) {
        float hv = h[k];
        const float* wr = Wo2 + (size_t)k * 7;
        #pragma unroll
        for (int o = 0; o < 7; o++) acc[o] += hv * wr[o];
    }
    #pragma unroll
    for (int o = 0; o < 7; o++)
        #pragma unroll
        for (int off = 16; off > 0; off >>= 1)
            acc[o] += __shfl_xor_sync(0xffffffffu, acc[o], off);
    float msk = (m1[w] != 0u && m2[w] != 0u) ? 1.0f : 0.0f;
    if (lane < 7) out[(size_t)w * 7 + lane] = (acc[lane] + bo2[lane]) * msk;
}

// ================= host launch =================
extern "C" void kernel_launch(void* const* d_in, const int* in_sizes, int n_in,
                              void* d_out, int out_size) {
    const float* nodes = (const float*)d_in[0];
    const float* arcs  = (const float*)d_in[1];
    const unsigned int* set_mask = (const unsigned int*)d_in[2];
    const unsigned int* output_mask = (const unsigned int*)d_in[3];
    const int* adj_src = (const int*)d_in[4];
    const int* adj_dst = (const int*)d_in[5];
    const float* adj_vals = (const float*)d_in[6];
    const int* an_dst = (const int*)d_in[7];
    const float* an_vals = (const float*)d_in[8];
    const float* state_init = (const float*)d_in[9];
    const float* Ws1 = (const float*)d_in[10];
    const float* bs1 = (const float*)d_in[11];
    const float* Ws2 = (const float*)d_in[12];
    const float* bs2 = (const float*)d_in[13];
    const float* Wo1 = (const float*)d_in[14];
    const float* bo1 = (const float*)d_in[15];
    const float* Wo2 = (const float*)d_in[16];
    const float* bo2 = (const float*)d_in[17];
    float* out = (float*)d_out;

    int Nn = in_sizes[0] / 128;   // 50000
    int E  = in_sizes[4];         // 640000

    float *p_agg_states, *p_base, *p_h1f, *p_state, *p_tmp;
    int* p_done;
    __nv_bfloat16 *p_ws1t_h, *p_ws1t_l, *p_ws2t_h, *p_ws2t_l, *p_wo1t_h, *p_wo1t_l;
    float *p_agg_nodes, *p_agg_arcs;
    cudaGetSymbolAddress((void**)&p_agg_states, g_agg_states);
    cudaGetSymbolAddress((void**)&p_base, g_base);
    cudaGetSymbolAddress((void**)&p_h1f, g_h1f);
    cudaGetSymbolAddress((void**)&p_state, g_state);
    cudaGetSymbolAddress((void**)&p_tmp, g_tmp);
    cudaGetSymbolAddress((void**)&p_done, g_done);
    cudaGetSymbolAddress((void**)&p_agg_nodes, g_agg_nodes);
    cudaGetSymbolAddress((void**)&p_agg_arcs, g_agg_arcs);
    cudaGetSymbolAddress((void**)&p_ws1t_h, g_ws1t_h);
    cudaGetSymbolAddress((void**)&p_ws1t_l, g_ws1t_l);
    cudaGetSymbolAddress((void**)&p_ws2t_h, g_ws2t_h);
    cudaGetSymbolAddress((void**)&p_ws2t_l, g_ws2t_l);
    cudaGetSymbolAddress((void**)&p_wo1t_h, g_wo1t_h);
    cudaGetSymbolAddress((void**)&p_wo1t_l, g_wo1t_l);

    auto kBase  = gemm_db<3, false, false, true,  128>;
    auto kIter1 = gemm_db<2, true,  true,  false, 128>;
    auto kIter2 = gemm_db<1, true,  false, true,  128>;
    auto kFinal = gemm_db<2, true,  false, true,  128>;
    const int SMEM = 40960 + 3 * 128 * 160;  // 102400
    cudaFuncSetAttribute(kBase,  cudaFuncAttributeMaxDynamicSharedMemorySize, SMEM);
    cudaFuncSetAttribute(kIter1, cudaFuncAttributeMaxDynamicSharedMemorySize, SMEM);
    cudaFuncSetAttribute(kIter2, cudaFuncAttributeMaxDynamicSharedMemorySize, SMEM);
    cudaFuncSetAttribute(kFinal, cudaFuncAttributeMaxDynamicSharedMemorySize, SMEM);

    int edge2Blocks = (2 * E + 255) / 256;
    int nodeWarpBlocks = (Nn * 32 + 255) / 256;
    int mtiles = (Nn + 127) / 128;
    dim3 g512(4, mtiles);
    dim3 g128(1, mtiles);

    // ---- one-time setup ----
    setup_kernel<<<nodeWarpBlocks, 256>>>(state_init, Nn);
    hist2_kernel<<<edge2Blocks, 256>>>(adj_dst, an_dst, E);
    scan2_kernel<<<2, 1024>>>(Nn);
    fill2_kernel<<<edge2Blocks, 256>>>(adj_src, adj_dst, adj_vals, an_dst, an_vals, E);
    transpose_all_kernel<<<(491520 + 255) / 256, 256>>>(Ws1, Ws2, Wo1);
    gather_arcs_kernel<<<nodeWarpBlocks, 256>>>(arcs, Nn);
    scatter_csr_kernel<<<nodeWarpBlocks, 256>>>(nodes, p_agg_nodes, Nn, -1);

    // base = bs1 + nodes@Ws1[128:256] + agg_nodes@Ws1[384:512] + agg_arcs@Ws1[512:576]
    kBase<<<g512, 256, SMEM>>>(
        Nn, 512, p_ws1t_h, p_ws1t_l, 576, bs1, nullptr, p_base,
        nodes, 128, 128,
        p_agg_nodes, 128, 384,
        p_agg_arcs, 64, 512, nullptr);

    // ---- fixed-point loop: 4 launches/iter (finalize fused into scatter) ----
    for (int it = 0; it < 10; ++it) {
        scatter_csr_kernel<<<nodeWarpBlocks, 256>>>(p_state, p_agg_states, Nn, it);
        kIter1<<<g512, 256, SMEM>>>(
            Nn, 512, p_ws1t_h, p_ws1t_l, 576, nullptr, p_base, p_h1f,
            p_state, 128, 0,
            p_agg_states, 128, 256,
            nullptr, 0, 0, p_done);
        kIter2<<<g128, 256, SMEM>>>(
            Nn, 128, p_ws2t_h, p_ws2t_l, 512, bs2, nullptr, p_tmp,
            p_h1f, 512, 0,
            nullptr, 0, 0,
            nullptr, 0, 0, p_done);
        commit_check_kernel<<<nodeWarpBlocks, 256>>>(Nn, it);
    }

    // h1f = tanh(state@Wo1[0:128] + nodes@Wo1[128:256] + bo1)
    kFinal<<<g512, 256, SMEM>>>(
        Nn, 512, p_wo1t_h, p_wo1t_l, 256, bo1, nullptr, p_h1f,
        p_state, 128, 0,
        nodes, 128, 128,
        nullptr, 0, 0, nullptr);

    out_kernel<<<nodeWarpBlocks, 256>>>(Wo2, bo2, set_mask, output_mask, out, Nn);
}